// round 14
// baseline (speedup 1.0000x reference)
#include <cuda_runtime.h>
#include <cuda_fp16.h>
#include <cstdint>
#include <cstring>

// ============================================================================
// Problem constants
// ============================================================================
static constexpr int NROWS   = 1048576;
static constexpr int H       = 128;
static constexpr int L       = 16;
static constexpr int THREADS = 256;
static constexpr int ROWS    = 256;    // per CTA: two 128-row tiles

// Padded row: 128 halves + 8 pad = 272 bytes -> conflict-free ldmatrix.
static constexpr int SROW  = 272;
static constexpr int WTILE = 128 * SROW;        // one 128x128 fp16 matrix: 34816 B
static constexpr int WHALF = 64 * SROW;         // one wn-group's half: 17408 B

// SMEM layout (byte offsets) -- sized for 2 CTAs/SM
static constexpr int OFF_H0   = 0;                       // tile0 h (fp16)
static constexpr int OFF_H1   = OFF_H0 + WTILE;          // 34816 tile1 h
static constexpr int OFF_W    = OFF_H1 + WTILE;          // 69632 single W buffer
static constexpr int OFF_BIAS = OFF_W + WTILE;           // 104448
static constexpr int OFF_WOUT = OFF_BIAS + L * H * 4;    // 112640
static constexpr int OFF_BOUT = OFF_WOUT + 2 * H * 4;    // 113664
static constexpr int SMEM_BYTES = OFF_BOUT + 16;         // 113680 (~111 KB)

// Plain fp16 W image, padded [n][k] rows (row n: W[n][k] at n*SROW + 2k)
__device__ __align__(128) unsigned char g_w[(size_t)L * WTILE];

// ============================================================================
// PTX helpers
// ============================================================================
__device__ __forceinline__ uint32_t smem_to_u32(const void* p) {
    uint32_t a;
    asm("{ .reg .u64 t; cvta.to.shared.u64 t, %1; cvt.u32.u64 %0, t; }"
        : "=r"(a) : "l"(p));
    return a;
}

#define LDSM_X4(r, addr) \
    asm volatile("ldmatrix.sync.aligned.m8n8.x4.shared.b16 {%0,%1,%2,%3}, [%4];" \
        : "=r"((r)[0]), "=r"((r)[1]), "=r"((r)[2]), "=r"((r)[3]) : "r"(addr))

#define MMA16816(c, a, b0, b1) \
    asm volatile("mma.sync.aligned.m16n8k16.row.col.f32.f16.f16.f32 " \
        "{%0,%1,%2,%3}, {%4,%5,%6,%7}, {%8,%9}, {%0,%1,%2,%3};" \
        : "+f"((c)[0]), "+f"((c)[1]), "+f"((c)[2]), "+f"((c)[3]) \
        : "r"((a)[0]), "r"((a)[1]), "r"((a)[2]), "r"((a)[3]), "r"(b0), "r"(b1))

// 64-thread barrier: the two warps sharing a row band (ids 1..4)
#define BAR_BAND(id) \
    asm volatile("bar.sync %0, 64;" :: "r"(id) : "memory")
// 128-thread barrier: the four warps of one wn group (ids 5..6)
#define BAR_GROUP(id) \
    asm volatile("bar.sync %0, 128;" :: "r"(id) : "memory")

__device__ __forceinline__ void cp16(uint32_t dst, const void* src) {
    asm volatile("cp.async.cg.shared.global [%0], [%1], 16;" :: "r"(dst), "l"(src));
}
#define CP_COMMIT() asm volatile("cp.async.commit_group;" ::: "memory")
#define CP_WAIT0()  asm volatile("cp.async.wait_group 0;" ::: "memory")

__device__ __forceinline__ uint32_t h2u(__half2 h) {
    uint32_t u; memcpy(&u, &h, 4); return u;
}

// ============================================================================
// Prep kernel: W -> fp16, padded [n][k] layout per layer
// ============================================================================
__global__ void prep_w_kernel(const float* __restrict__ W) {
    const int l = blockIdx.x;
    const float* Wl = W + (size_t)l * H * H;
    unsigned char* dst = g_w + (size_t)l * WTILE;
    for (int i = threadIdx.x; i < H * H; i += blockDim.x) {
        const int n = i >> 7, k = i & 127;
        *(__half*)(dst + n * SROW + 2 * k) = __float2half_rn(Wl[i]);
    }
}

// cp.async one wn-group's W half (rows 64*wn..64*wn+63) using 128 threads
__device__ __forceinline__ void load_w_half(uint32_t dst_smem, int l, int wn, int gtid) {
    const size_t base = (size_t)l * WTILE + (size_t)wn * WHALF;
    const unsigned char* src = g_w + base;
    const uint32_t dst = dst_smem + (uint32_t)wn * WHALF;
#pragma unroll
    for (int i = 0; i < 9; i++) {
        const int idx = gtid + i * 128;
        if (idx < WHALF / 16) cp16(dst + idx * 16, src + idx * 16);
    }
}

// ============================================================================
// MMA for one 128-row tile: acc = bias + h @ W_l^T
// (bias folded into accumulator init; LDS latency hidden by the k-loop)
// ============================================================================
__device__ __forceinline__ void mma_tile(float acc[2][8][4], uint32_t ha, uint32_t wb,
                                         const float* __restrict__ bl, int ec) {
#pragma unroll
    for (int nt = 0; nt < 8; nt++) {
        const float2 t = *(const float2*)(bl + ec + 8 * nt);
#pragma unroll
        for (int mt = 0; mt < 2; mt++) {
            acc[mt][nt][0] = t.x; acc[mt][nt][1] = t.y;
            acc[mt][nt][2] = t.x; acc[mt][nt][3] = t.y;
        }
    }

#pragma unroll
    for (int ks = 0; ks < 8; ks++) {
        const uint32_t kb = ks * 32;
        uint32_t af[2][4], bf[4][4];
#pragma unroll
        for (int mt = 0; mt < 2; mt++)
            LDSM_X4(af[mt], ha + mt * (16 * SROW) + kb);
#pragma unroll
        for (int ng = 0; ng < 4; ng++)
            LDSM_X4(bf[ng], wb + ng * (16 * SROW) + kb);

#pragma unroll
        for (int mt = 0; mt < 2; mt++)
#pragma unroll
            for (int ng = 0; ng < 4; ng++) {
                MMA16816(acc[mt][2 * ng],     af[mt], bf[ng][0], bf[ng][1]);
                MMA16816(acc[mt][2 * ng + 1], af[mt], bf[ng][2], bf[ng][3]);
            }
    }
}

// ============================================================================
// Epilogue: acc (bias already included) -> relu -> fp16 h tile
// ============================================================================
__device__ __forceinline__ void epi_h(const float acc[2][8][4],
                                      unsigned char* hbase, int er, int ec) {
#pragma unroll
    for (int mt = 0; mt < 2; mt++)
#pragma unroll
        for (int nt = 0; nt < 8; nt++) {
            const float v0 = fmaxf(acc[mt][nt][0], 0.f);
            const float v1 = fmaxf(acc[mt][nt][1], 0.f);
            const float v2 = fmaxf(acc[mt][nt][2], 0.f);
            const float v3 = fmaxf(acc[mt][nt][3], 0.f);
            const int r = er + mt * 16;
            const int c = ec + nt * 8;
            *(uint32_t*)(hbase + r * SROW + c * 2)       = h2u(__floats2half2_rn(v0, v1));
            *(uint32_t*)(hbase + (r + 8) * SROW + c * 2) = h2u(__floats2half2_rn(v2, v3));
        }
}

// ============================================================================
// Main fused MLP kernel: occ 2, sub-CTA barriers, bias-in-init epilogue
// ============================================================================
__global__ void __launch_bounds__(THREADS, 2)
mlp_main(const float* __restrict__ x, const float* __restrict__ b,
         const float* __restrict__ Wout, const float* __restrict__ bout,
         float* __restrict__ out) {
    extern __shared__ unsigned char smem[];
    const uint32_t sb = smem_to_u32(smem);
    const int tid = threadIdx.x;
    const int lane = tid & 31;
    const int wid = tid >> 5;
    const int wm = wid & 3;      // 4 m-warps x 32 rows (row band)
    const int wn = wid >> 2;     // 2 n-warps x 64 cols (W half group; contiguous warps)
    const int gtid = tid & 127;  // thread index within wn group

    // ---- stage fixed tables ----
    {
        const float4* bs = (const float4*)b;
        float4* bd = (float4*)(smem + OFF_BIAS);
        bd[tid] = bs[tid];
        bd[tid + 256] = bs[tid + 256];
        if (tid < 64) ((float4*)(smem + OFF_WOUT))[tid] = ((const float4*)Wout)[tid];
        if (tid < 2)  ((float*)(smem + OFF_BOUT))[tid] = bout[tid];
    }

    // ---- kick W[0] copy: each wn group loads its own half ----
    load_w_half(sb + OFF_W, 0, wn, gtid);
    CP_COMMIT();

    // ---- prologue: x -> h0/h1 fp16 in SMEM ----
    {
        const float4* xs = (const float4*)(x + (size_t)blockIdx.x * ROWS * H);
#pragma unroll
        for (int i = 0; i < 32; i++) {
            const int idx = tid + i * THREADS;     // 0..8191
            const int r = idx >> 5, c = idx & 31;  // row 0..255, float4 idx
            const float4 v = xs[idx];
            unsigned char* hb = smem + (r < 128 ? OFF_H0 : OFF_H1);
            *(uint2*)(hb + (r & 127) * SROW + c * 8) =
                make_uint2(h2u(__floats2half2_rn(v.x, v.y)),
                           h2u(__floats2half2_rn(v.z, v.w)));
        }
    }
    __syncthreads();   // prologue h writes (cross-band) visible

    // ---- per-thread ldmatrix address roles ----
    const int arow = (lane & 7) | (((lane >> 3) & 1) << 3);
    const int achk = lane >> 4;
    const uint32_t aoff = (uint32_t)((32 * wm + arow) * SROW + achk * 16);

    const int bg = lane >> 3;
    const int bn = ((bg >> 1) << 3) | (lane & 7);
    const int bchk = bg & 1;
    const uint32_t boff = (uint32_t)((64 * wn + bn) * SROW + bchk * 16);

    // epilogue roles
    const int er = 32 * wm + (lane >> 2);
    const int ec = 64 * wn + 2 * (lane & 3);

    const float* bias = (const float*)(smem + OFF_BIAS);
    const uint32_t wb = sb + OFF_W + boff;
    const int band_bar  = 1 + wm;   // ids 1..4, 64 threads
    const int group_bar = 5 + wn;   // ids 5..6, 128 threads

    float acc[2][8][4];

#pragma unroll 1
    for (int l = 0; l < L; l++) {
        const float* bl = bias + l * H;
        CP_WAIT0();              // my group's W[l] half committed (per-thread)
        BAR_GROUP(group_bar);    // W[l] half visible group-wide
        BAR_BAND(band_bar);      // prev-layer h writes visible within band

        // ---- tile0: MMA (bias-init), band sync, epilogue ----
        mma_tile(acc, sb + OFF_H0 + aoff, wb, bl, ec);
        BAR_BAND(band_bar);
        epi_h(acc, smem + OFF_H0, er, ec);

        // ---- tile1: MMA; band sync THEN group sync; prefetch; epilogue ----
        mma_tile(acc, sb + OFF_H1 + aoff, wb, bl, ec);
        BAR_BAND(band_bar);      // band partner's h1 reads retired
        BAR_GROUP(group_bar);    // group's W[l] half reads retired
        if (l + 1 < L) {
            load_w_half(sb + OFF_W, l + 1, wn, gtid);
            CP_COMMIT();
        }
        epi_h(acc, smem + OFF_H1, er, ec);
    }

    __syncthreads();

    // ---- final projection: relu_h[256] (fp16) @ Wout.T + bout ----
    {
        const unsigned char* hb = smem + (tid < 128 ? OFF_H0 : OFF_H1);
        const uint2* hrow = (const uint2*)(hb + (tid & 127) * SROW);
        const float* wo = (const float*)(smem + OFF_WOUT);
        const float* bo = (const float*)(smem + OFF_BOUT);
        float o0 = bo[0], o1 = bo[1];
#pragma unroll
        for (int q = 0; q < 32; q++) {
            const uint2 u = hrow[q];
            __half2 p0, p1;
            memcpy(&p0, &u.x, 4);
            memcpy(&p1, &u.y, 4);
            const float2 f0 = __half22float2(p0);
            const float2 f1 = __half22float2(p1);
            const int k = q * 4;
            o0 = fmaf(f0.x, wo[k],     o0); o1 = fmaf(f0.x, wo[H + k],     o1);
            o0 = fmaf(f0.y, wo[k + 1], o0); o1 = fmaf(f0.y, wo[H + k + 1], o1);
            o0 = fmaf(f1.x, wo[k + 2], o0); o1 = fmaf(f1.x, wo[H + k + 2], o1);
            o0 = fmaf(f1.y, wo[k + 3], o0); o1 = fmaf(f1.y, wo[H + k + 3], o1);
        }
        ((float2*)out)[(size_t)blockIdx.x * ROWS + tid] = make_float2(o0, o1);
    }
}

// ============================================================================
// Launch
// ============================================================================
extern "C" void kernel_launch(void* const* d_in, const int* in_sizes, int n_in,
                              void* d_out, int out_size) {
    const float* x    = (const float*)d_in[0];
    const float* W    = (const float*)d_in[1];
    const float* b    = (const float*)d_in[2];
    const float* Wout = (const float*)d_in[3];
    const float* bout = (const float*)d_in[4];
    float* out = (float*)d_out;

    prep_w_kernel<<<L, 256>>>(W);

    cudaFuncSetAttribute(mlp_main, cudaFuncAttributeMaxDynamicSharedMemorySize, SMEM_BYTES);
    mlp_main<<<NROWS / ROWS, THREADS, SMEM_BYTES>>>(x, b, Wout, bout, out);
}

// round 15
// speedup vs baseline: 1.0023x; 1.0023x over previous
#include <cuda_runtime.h>
#include <cuda_fp16.h>
#include <cstdint>
#include <cstring>

// ============================================================================
// Problem constants
// ============================================================================
static constexpr int NROWS   = 1048576;
static constexpr int H       = 128;
static constexpr int L       = 16;
static constexpr int THREADS = 256;
static constexpr int ROWS    = 256;    // per CTA: two 128-row tiles

// Padded row: 128 halves + 8 pad = 272 bytes -> conflict-free ldmatrix.
static constexpr int SROW  = 272;
static constexpr int WTILE = 128 * SROW;        // one 128x128 fp16 matrix: 34816 B
static constexpr int WHALF = 64 * SROW;         // one wn-group's half: 17408 B

// SMEM layout (byte offsets) -- sized for 2 CTAs/SM
static constexpr int OFF_H0   = 0;                       // tile0 h (fp16)
static constexpr int OFF_H1   = OFF_H0 + WTILE;          // 34816 tile1 h
static constexpr int OFF_W    = OFF_H1 + WTILE;          // 69632 single W buffer
static constexpr int OFF_BIAS = OFF_W + WTILE;           // 104448
static constexpr int OFF_WOUT = OFF_BIAS + L * H * 4;    // 112640
static constexpr int OFF_BOUT = OFF_WOUT + 2 * H * 4;    // 113664
static constexpr int SMEM_BYTES = OFF_BOUT + 16;         // 113680 (~111 KB)

// Plain fp16 W image, padded [n][k] rows (row n: W[n][k] at n*SROW + 2k)
__device__ __align__(128) unsigned char g_w[(size_t)L * WTILE];

// ============================================================================
// PTX helpers
// ============================================================================
__device__ __forceinline__ uint32_t smem_to_u32(const void* p) {
    uint32_t a;
    asm("{ .reg .u64 t; cvta.to.shared.u64 t, %1; cvt.u32.u64 %0, t; }"
        : "=r"(a) : "l"(p));
    return a;
}

#define LDSM_X4(r, addr) \
    asm volatile("ldmatrix.sync.aligned.m8n8.x4.shared.b16 {%0,%1,%2,%3}, [%4];" \
        : "=r"((r)[0]), "=r"((r)[1]), "=r"((r)[2]), "=r"((r)[3]) : "r"(addr))

#define MMA16816(c, a, b0, b1) \
    asm volatile("mma.sync.aligned.m16n8k16.row.col.f32.f16.f16.f32 " \
        "{%0,%1,%2,%3}, {%4,%5,%6,%7}, {%8,%9}, {%0,%1,%2,%3};" \
        : "+f"((c)[0]), "+f"((c)[1]), "+f"((c)[2]), "+f"((c)[3]) \
        : "r"((a)[0]), "r"((a)[1]), "r"((a)[2]), "r"((a)[3]), "r"(b0), "r"(b1))

// 64-thread barrier: the two warps sharing a row band (ids 1..4)
#define BAR_BAND(id) \
    asm volatile("bar.sync %0, 64;" :: "r"(id) : "memory")
// 128-thread barrier: the four warps of one wn group (ids 5..6)
#define BAR_GROUP(id) \
    asm volatile("bar.sync %0, 128;" :: "r"(id) : "memory")

__device__ __forceinline__ void cp16(uint32_t dst, const void* src) {
    asm volatile("cp.async.cg.shared.global [%0], [%1], 16;" :: "r"(dst), "l"(src));
}
#define CP_COMMIT() asm volatile("cp.async.commit_group;" ::: "memory")
#define CP_WAIT0()  asm volatile("cp.async.wait_group 0;" ::: "memory")

__device__ __forceinline__ uint32_t h2u(__half2 h) {
    uint32_t u; memcpy(&u, &h, 4); return u;
}

// ============================================================================
// Prep kernel: W -> fp16, padded [n][k] layout per layer
// ============================================================================
__global__ void prep_w_kernel(const float* __restrict__ W) {
    const int l = blockIdx.x;
    const float* Wl = W + (size_t)l * H * H;
    unsigned char* dst = g_w + (size_t)l * WTILE;
    for (int i = threadIdx.x; i < H * H; i += blockDim.x) {
        const int n = i >> 7, k = i & 127;
        *(__half*)(dst + n * SROW + 2 * k) = __float2half_rn(Wl[i]);
    }
}

// cp.async one wn-group's W half (rows 64*wn..64*wn+63) using 128 threads
__device__ __forceinline__ void load_w_half(uint32_t dst_smem, int l, int wn, int gtid) {
    const size_t base = (size_t)l * WTILE + (size_t)wn * WHALF;
    const unsigned char* src = g_w + base;
    const uint32_t dst = dst_smem + (uint32_t)wn * WHALF;
#pragma unroll
    for (int i = 0; i < 9; i++) {
        const int idx = gtid + i * 128;
        if (idx < WHALF / 16) cp16(dst + idx * 16, src + idx * 16);
    }
}

// ============================================================================
// MMA for one 128-row tile: acc = h @ W_l^T   (single fp16 pass, fp32 acc)
// ============================================================================
__device__ __forceinline__ void mma_tile(float acc[2][8][4], uint32_t ha, uint32_t wb) {
#pragma unroll
    for (int mt = 0; mt < 2; mt++)
#pragma unroll
        for (int nt = 0; nt < 8; nt++)
#pragma unroll
            for (int q = 0; q < 4; q++) acc[mt][nt][q] = 0.f;

#pragma unroll
    for (int ks = 0; ks < 8; ks++) {
        const uint32_t kb = ks * 32;
        uint32_t af[2][4], bf[4][4];
#pragma unroll
        for (int mt = 0; mt < 2; mt++)
            LDSM_X4(af[mt], ha + mt * (16 * SROW) + kb);
#pragma unroll
        for (int ng = 0; ng < 4; ng++)
            LDSM_X4(bf[ng], wb + ng * (16 * SROW) + kb);

#pragma unroll
        for (int mt = 0; mt < 2; mt++)
#pragma unroll
            for (int ng = 0; ng < 4; ng++) {
                MMA16816(acc[mt][2 * ng],     af[mt], bf[ng][0], bf[ng][1]);
                MMA16816(acc[mt][2 * ng + 1], af[mt], bf[ng][2], bf[ng][3]);
            }
    }
}

// ============================================================================
// Fused MMA(tile1) + interleaved stores of tile0's packed epilogue.
// Per-ng B fragments (4 live regs) keep peak pressure under the 128 cap.
// ============================================================================
__device__ __forceinline__ void mma_tile_st(float acc[2][8][4], uint32_t ha, uint32_t wb,
                                            const uint32_t p[32], unsigned char* h0base,
                                            int er, int ec) {
#pragma unroll
    for (int mt = 0; mt < 2; mt++)
#pragma unroll
        for (int nt = 0; nt < 8; nt++)
#pragma unroll
            for (int q = 0; q < 4; q++) acc[mt][nt][q] = 0.f;

#pragma unroll
    for (int ks = 0; ks < 8; ks++) {
        const uint32_t kb = ks * 32;
        uint32_t af[2][4];
#pragma unroll
        for (int mt = 0; mt < 2; mt++)
            LDSM_X4(af[mt], ha + mt * (16 * SROW) + kb);
#pragma unroll
        for (int ng = 0; ng < 4; ng++) {
            uint32_t bf[4];
            LDSM_X4(bf, wb + ng * (16 * SROW) + kb);
#pragma unroll
            for (int mt = 0; mt < 2; mt++) {
                MMA16816(acc[mt][2 * ng],     af[mt], bf[0], bf[1]);
                MMA16816(acc[mt][2 * ng + 1], af[mt], bf[2], bf[3]);
            }
        }
        // dribble out 4 of tile0's packed stores per k-step (32 total)
#pragma unroll
        for (int i = 4 * ks; i < 4 * ks + 4; i++) {
            const int mt = i >> 4, rem = i & 15, nt = rem >> 1, j = rem & 1;
            *(uint32_t*)(h0base + (er + mt * 16 + j * 8) * SROW + (ec + nt * 8) * 2) = p[i];
        }
    }
}

// ============================================================================
// pack: acc -> bias + relu -> 32 packed fp16x2 registers (frees acc)
// ============================================================================
__device__ __forceinline__ void pack_tile(const float acc[2][8][4],
                                          const float* __restrict__ bl,
                                          uint32_t p[32], int ec) {
#pragma unroll
    for (int mt = 0; mt < 2; mt++)
#pragma unroll
        for (int nt = 0; nt < 8; nt++) {
            const float b0 = bl[ec + 8 * nt], b1 = bl[ec + 8 * nt + 1];
            const float v0 = fmaxf(acc[mt][nt][0] + b0, 0.f);
            const float v1 = fmaxf(acc[mt][nt][1] + b1, 0.f);
            const float v2 = fmaxf(acc[mt][nt][2] + b0, 0.f);
            const float v3 = fmaxf(acc[mt][nt][3] + b1, 0.f);
            p[mt * 16 + nt * 2]     = h2u(__floats2half2_rn(v0, v1));
            p[mt * 16 + nt * 2 + 1] = h2u(__floats2half2_rn(v2, v3));
        }
}

// ============================================================================
// Epilogue: acc -> bias + relu -> fp16 h tile
// ============================================================================
__device__ __forceinline__ void epi_h(const float acc[2][8][4],
                                      const float* __restrict__ bl,
                                      unsigned char* hbase, int er, int ec) {
#pragma unroll
    for (int mt = 0; mt < 2; mt++)
#pragma unroll
        for (int nt = 0; nt < 8; nt++) {
            const float b0 = bl[ec + 8 * nt], b1 = bl[ec + 8 * nt + 1];
            const float v0 = fmaxf(acc[mt][nt][0] + b0, 0.f);
            const float v1 = fmaxf(acc[mt][nt][1] + b1, 0.f);
            const float v2 = fmaxf(acc[mt][nt][2] + b0, 0.f);
            const float v3 = fmaxf(acc[mt][nt][3] + b1, 0.f);
            const int r = er + mt * 16;
            const int c = ec + nt * 8;
            *(uint32_t*)(hbase + r * SROW + c * 2)       = h2u(__floats2half2_rn(v0, v1));
            *(uint32_t*)(hbase + (r + 8) * SROW + c * 2) = h2u(__floats2half2_rn(v2, v3));
        }
}

// ============================================================================
// Main fused MLP kernel: occ 2, fused t1-MMA + t0-store phase
// ============================================================================
__global__ void __launch_bounds__(THREADS, 2)
mlp_main(const float* __restrict__ x, const float* __restrict__ b,
         const float* __restrict__ Wout, const float* __restrict__ bout,
         float* __restrict__ out) {
    extern __shared__ unsigned char smem[];
    const uint32_t sb = smem_to_u32(smem);
    const int tid = threadIdx.x;
    const int lane = tid & 31;
    const int wid = tid >> 5;
    const int wm = wid & 3;      // 4 m-warps x 32 rows (row band)
    const int wn = wid >> 2;     // 2 n-warps x 64 cols (W half group; contiguous warps)
    const int gtid = tid & 127;  // thread index within wn group

    // ---- stage fixed tables ----
    {
        const float4* bs = (const float4*)b;
        float4* bd = (float4*)(smem + OFF_BIAS);
        bd[tid] = bs[tid];
        bd[tid + 256] = bs[tid + 256];
        if (tid < 64) ((float4*)(smem + OFF_WOUT))[tid] = ((const float4*)Wout)[tid];
        if (tid < 2)  ((float*)(smem + OFF_BOUT))[tid] = bout[tid];
    }

    // ---- kick W[0] copy: each wn group loads its own half ----
    load_w_half(sb + OFF_W, 0, wn, gtid);
    CP_COMMIT();

    // ---- prologue: x -> h0/h1 fp16 in SMEM ----
    {
        const float4* xs = (const float4*)(x + (size_t)blockIdx.x * ROWS * H);
#pragma unroll
        for (int i = 0; i < 32; i++) {
            const int idx = tid + i * THREADS;     // 0..8191
            const int r = idx >> 5, c = idx & 31;  // row 0..255, float4 idx
            const float4 v = xs[idx];
            unsigned char* hb = smem + (r < 128 ? OFF_H0 : OFF_H1);
            *(uint2*)(hb + (r & 127) * SROW + c * 8) =
                make_uint2(h2u(__floats2half2_rn(v.x, v.y)),
                           h2u(__floats2half2_rn(v.z, v.w)));
        }
    }
    __syncthreads();   // prologue h writes (cross-band) visible

    // ---- per-thread ldmatrix address roles ----
    const int arow = (lane & 7) | (((lane >> 3) & 1) << 3);
    const int achk = lane >> 4;
    const uint32_t aoff = (uint32_t)((32 * wm + arow) * SROW + achk * 16);

    const int bg = lane >> 3;
    const int bn = ((bg >> 1) << 3) | (lane & 7);
    const int bchk = bg & 1;
    const uint32_t boff = (uint32_t)((64 * wn + bn) * SROW + bchk * 16);

    // epilogue roles
    const int er = 32 * wm + (lane >> 2);
    const int ec = 64 * wn + 2 * (lane & 3);

    const float* bias = (const float*)(smem + OFF_BIAS);
    const uint32_t wb = sb + OFF_W + boff;
    const int band_bar  = 1 + wm;   // ids 1..4, 64 threads
    const int group_bar = 5 + wn;   // ids 5..6, 128 threads

    float acc[2][8][4];
    uint32_t p[32];

#pragma unroll 1
    for (int l = 0; l < L; l++) {
        const float* bl = bias + l * H;
        CP_WAIT0();              // my group's W[l] half committed (per-thread)
        BAR_GROUP(group_bar);    // W[l] half visible group-wide
        BAR_BAND(band_bar);      // prev-layer h writes visible within band

        // ---- tile0: MMA, pack into registers (acc freed) ----
        mma_tile(acc, sb + OFF_H0 + aoff, wb);
        pack_tile(acc, bl, p, ec);
        BAR_BAND(band_bar);      // band partner's h0 reads retired

        // ---- tile1 MMA with tile0's stores interleaved ----
        mma_tile_st(acc, sb + OFF_H1 + aoff, wb, p, smem + OFF_H0, er, ec);
        BAR_BAND(band_bar);      // band partner's h1 reads retired
        BAR_GROUP(group_bar);    // group's W[l] half reads retired
        if (l + 1 < L) {
            load_w_half(sb + OFF_W, l + 1, wn, gtid);
            CP_COMMIT();
        }
        epi_h(acc, bl, smem + OFF_H1, er, ec);
    }

    __syncthreads();

    // ---- final projection: relu_h[256] (fp16) @ Wout.T + bout ----
    {
        const unsigned char* hb = smem + (tid < 128 ? OFF_H0 : OFF_H1);
        const uint2* hrow = (const uint2*)(hb + (tid & 127) * SROW);
        const float* wo = (const float*)(smem + OFF_WOUT);
        const float* bo = (const float*)(smem + OFF_BOUT);
        float o0 = bo[0], o1 = bo[1];
#pragma unroll
        for (int q = 0; q < 32; q++) {
            const uint2 u = hrow[q];
            __half2 p0, p1;
            memcpy(&p0, &u.x, 4);
            memcpy(&p1, &u.y, 4);
            const float2 f0 = __half22float2(p0);
            const float2 f1 = __half22float2(p1);
            const int k = q * 4;
            o0 = fmaf(f0.x, wo[k],     o0); o1 = fmaf(f0.x, wo[H + k],     o1);
            o0 = fmaf(f0.y, wo[k + 1], o0); o1 = fmaf(f0.y, wo[H + k + 1], o1);
            o0 = fmaf(f1.x, wo[k + 2], o0); o1 = fmaf(f1.x, wo[H + k + 2], o1);
            o0 = fmaf(f1.y, wo[k + 3], o0); o1 = fmaf(f1.y, wo[H + k + 3], o1);
        }
        ((float2*)out)[(size_t)blockIdx.x * ROWS + tid] = make_float2(o0, o1);
    }
}

// ============================================================================
// Launch
// ============================================================================
extern "C" void kernel_launch(void* const* d_in, const int* in_sizes, int n_in,
                              void* d_out, int out_size) {
    const float* x    = (const float*)d_in[0];
    const float* W    = (const float*)d_in[1];
    const float* b    = (const float*)d_in[2];
    const float* Wout = (const float*)d_in[3];
    const float* bout = (const float*)d_in[4];
    float* out = (float*)d_out;

    prep_w_kernel<<<L, 256>>>(W);

    cudaFuncSetAttribute(mlp_main, cudaFuncAttributeMaxDynamicSharedMemorySize, SMEM_BYTES);
    mlp_main<<<NROWS / ROWS, THREADS, SMEM_BYTES>>>(x, b, Wout, bout, out);
}

// round 17
// speedup vs baseline: 1.0198x; 1.0174x over previous
#include <cuda_runtime.h>
#include <cuda_fp16.h>
#include <cstdint>
#include <cstring>

// ============================================================================
// Problem constants
// ============================================================================
static constexpr int NROWS   = 1048576;
static constexpr int H       = 128;
static constexpr int L       = 16;
static constexpr int THREADS = 256;
static constexpr int ROWS    = 128;    // per CTA: 8 warps x 16 rows (full-N tiles)

// Padded row: 128 halves + 8 pad = 272 bytes -> conflict-free ldmatrix.
static constexpr int SROW  = 272;
static constexpr int WTILE = 128 * SROW;        // one 128x128 fp16 matrix: 34816 B

// SMEM layout: double-buffered W + tables (h lives in registers!)
static constexpr int OFF_W    = 0;                       // 2 x WTILE
static constexpr int OFF_BIAS = OFF_W + 2 * WTILE;       // 69632
static constexpr int OFF_WOUT = OFF_BIAS + L * H * 4;    // 77824
static constexpr int OFF_BOUT = OFF_WOUT + 2 * H * 4;    // 78848
static constexpr int SMEM_BYTES = OFF_BOUT + 16;         // 78864 (~77 KB, occ 2)

// Plain fp16 W image, padded [n][k] rows (row n: W[n][k] at n*SROW + 2k)
__device__ __align__(128) unsigned char g_w[(size_t)L * WTILE];

// ============================================================================
// PTX helpers
// ============================================================================
__device__ __forceinline__ uint32_t smem_to_u32(const void* p) {
    uint32_t a;
    asm("{ .reg .u64 t; cvta.to.shared.u64 t, %1; cvt.u32.u64 %0, t; }"
        : "=r"(a) : "l"(p));
    return a;
}

#define LDSM_X4(r, addr) \
    asm volatile("ldmatrix.sync.aligned.m8n8.x4.shared.b16 {%0,%1,%2,%3}, [%4];" \
        : "=r"((r)[0]), "=r"((r)[1]), "=r"((r)[2]), "=r"((r)[3]) : "r"(addr))

#define MMA16816(c, a, b0, b1) \
    asm volatile("mma.sync.aligned.m16n8k16.row.col.f32.f16.f16.f32 " \
        "{%0,%1,%2,%3}, {%4,%5,%6,%7}, {%8,%9}, {%0,%1,%2,%3};" \
        : "+f"((c)[0]), "+f"((c)[1]), "+f"((c)[2]), "+f"((c)[3]) \
        : "r"((a)[0]), "r"((a)[1]), "r"((a)[2]), "r"((a)[3]), "r"(b0), "r"(b1))

__device__ __forceinline__ void cp16(uint32_t dst, const void* src) {
    asm volatile("cp.async.cg.shared.global [%0], [%1], 16;" :: "r"(dst), "l"(src));
}
#define CP_COMMIT() asm volatile("cp.async.commit_group;" ::: "memory")
#define CP_WAIT0()  asm volatile("cp.async.wait_group 0;" ::: "memory")

__device__ __forceinline__ uint32_t h2u(__half2 h) {
    uint32_t u; memcpy(&u, &h, 4); return u;
}

// ============================================================================
// Prep kernel: W -> fp16, padded [n][k] layout per layer
// ============================================================================
__global__ void prep_w_kernel(const float* __restrict__ W) {
    const int l = blockIdx.x;
    const float* Wl = W + (size_t)l * H * H;
    unsigned char* dst = g_w + (size_t)l * WTILE;
    for (int i = threadIdx.x; i < H * H; i += blockDim.x) {
        const int n = i >> 7, k = i & 127;
        *(__half*)(dst + n * SROW + 2 * k) = __float2half_rn(Wl[i]);
    }
}

// cp.async one layer's full W tile (34816 B = 2176 x 16B), 256 threads
__device__ __forceinline__ void load_w(uint32_t dst_smem, int l, int tid) {
    const unsigned char* src = g_w + (size_t)l * WTILE;
#pragma unroll
    for (int i = 0; i < 9; i++) {
        const int idx = tid + i * THREADS;
        if (idx < WTILE / 16) cp16(dst_smem + idx * 16, src + idx * 16);
    }
}

// ============================================================================
// Main fused MLP kernel: h register-resident across all layers.
// Warp tile: 16 rows x 128 cols. acc (fp32) quads re-pack in-lane into the
// next layer's A fragments (C-frag <-> A-frag layout identity).
// ============================================================================
__global__ void __launch_bounds__(THREADS, 2)
mlp_main(const float* __restrict__ x, const float* __restrict__ b,
         const float* __restrict__ Wout, const float* __restrict__ bout,
         float* __restrict__ out) {
    extern __shared__ unsigned char smem[];
    const uint32_t sb = smem_to_u32(smem);
    const int tid = threadIdx.x;
    const int lane = tid & 31;
    const int wid = tid >> 5;          // 0..7, owns rows 16*wid..16*wid+15
    const int q2 = 2 * (lane & 3);     // col offset within an 8-wide n-tile

    // ---- kick W[0] copy into buffer 0 ----
    load_w(sb + OFF_W, 0, tid);
    CP_COMMIT();

    // ---- stage fixed tables (b is L*H = 2048 floats = 512 float4) ----
    {
        const float4* bs = (const float4*)b;
        float4* bd = (float4*)(smem + OFF_BIAS);
        bd[tid] = bs[tid];
        bd[tid + 256] = bs[tid + 256];
        if (tid < 64) ((float4*)(smem + OFF_WOUT))[tid] = ((const float4*)Wout)[tid];
        if (tid < 2)  ((float*)(smem + OFF_BOUT))[tid] = bout[tid];
    }

    // ---- stage x (fp16) into buffer 1, then ldmatrix into ap registers ----
    {
        const float4* xs = (const float4*)(x + (size_t)blockIdx.x * ROWS * H);
        unsigned char* xb = smem + OFF_W + WTILE;
#pragma unroll
        for (int i = 0; i < 16; i++) {
            const int idx = tid + i * THREADS;     // 0..4095
            const int r = idx >> 5, c = idx & 31;  // row 0..127, float4 idx
            const float4 v = xs[idx];
            *(uint2*)(xb + r * SROW + c * 8) =
                make_uint2(h2u(__floats2half2_rn(v.x, v.y)),
                           h2u(__floats2half2_rn(v.z, v.w)));
        }
    }
    __syncthreads();   // x staged

    // A-fragment ldmatrix addressing (16x16 per x4)
    const int arow = (lane & 7) | (((lane >> 3) & 1) << 3);
    const int achk = lane >> 4;
    uint32_t ap[8][4];   // packed fp16x2 h fragments, one per 16-wide k-chunk
    {
        const uint32_t xa = sb + OFF_W + WTILE
                          + (uint32_t)((16 * wid + arow) * SROW + achk * 16);
#pragma unroll
        for (int kc = 0; kc < 8; kc++)
            LDSM_X4(ap[kc], xa + kc * 32);
    }
    __syncthreads();   // buffer-1 x reads retired (W[1] will overwrite it)

    // B-fragment ldmatrix addressing
    const int bg = lane >> 3;
    const int bn = ((bg >> 1) << 3) | (lane & 7);
    const int bchk = bg & 1;
    const uint32_t wboff = (uint32_t)(bn * SROW + bchk * 16);

    const float* bias = (const float*)(smem + OFF_BIAS);
    float acc[16][4];

#pragma unroll 1
    for (int l = 0; l < L; l++) {
        CP_WAIT0();              // W[l] copies (this thread's) done
        __syncthreads();         // W[l] visible; prior buffer readers retired

        // prefetch W[l+1] into the other buffer (readers retired by sync)
        if (l + 1 < L) {
            load_w(sb + OFF_W + (uint32_t)((l + 1) & 1) * WTILE, l + 1, tid);
            CP_COMMIT();
        }

        const uint32_t wb = sb + OFF_W + (uint32_t)(l & 1) * WTILE + wboff;

        // ---- MMA: 16 rows x 128 cols, A from registers, B from smem ----
#pragma unroll
        for (int nt = 0; nt < 16; nt++)
#pragma unroll
            for (int q = 0; q < 4; q++) acc[nt][q] = 0.f;

#pragma unroll
        for (int kc = 0; kc < 8; kc++) {
            const uint32_t kb = kc * 32;
#pragma unroll
            for (int tp = 0; tp < 8; tp++) {
                uint32_t bf[4];
                LDSM_X4(bf, wb + tp * (16 * SROW) + kb);
                MMA16816(acc[2 * tp],     ap[kc], bf[0], bf[1]);
                MMA16816(acc[2 * tp + 1], ap[kc], bf[2], bf[3]);
            }
        }

        if (l < L - 1) {
            // ---- pack: bias + relu -> next layer's A fragments (in-lane) ----
            const float* bl = bias + l * H;
#pragma unroll
            for (int kc = 0; kc < 8; kc++) {
                const int c0 = 16 * kc + q2;
                const float b0 = bl[c0],     b1 = bl[c0 + 1];
                const float b2 = bl[c0 + 8], b3 = bl[c0 + 9];
                ap[kc][0] = h2u(__floats2half2_rn(fmaxf(acc[2 * kc][0] + b0, 0.f),
                                                  fmaxf(acc[2 * kc][1] + b1, 0.f)));
                ap[kc][1] = h2u(__floats2half2_rn(fmaxf(acc[2 * kc][2] + b0, 0.f),
                                                  fmaxf(acc[2 * kc][3] + b1, 0.f)));
                ap[kc][2] = h2u(__floats2half2_rn(fmaxf(acc[2 * kc + 1][0] + b2, 0.f),
                                                  fmaxf(acc[2 * kc + 1][1] + b3, 0.f)));
                ap[kc][3] = h2u(__floats2half2_rn(fmaxf(acc[2 * kc + 1][2] + b2, 0.f),
                                                  fmaxf(acc[2 * kc + 1][3] + b3, 0.f)));
            }
        }
    }

    // ---- final: bias + relu + projection to 2 outputs, quad-shuffle reduce --
    {
        const float* bl = bias + (L - 1) * H;
        const float* wo = (const float*)(smem + OFF_WOUT);
        const float* bo = (const float*)(smem + OFF_BOUT);
        float o0a = 0.f, o1a = 0.f, o0b = 0.f, o1b = 0.f;
#pragma unroll
        for (int nt = 0; nt < 16; nt++) {
            const int c = 8 * nt + q2;
            const float b0 = bl[c], b1 = bl[c + 1];
            const float w00 = wo[c], w01 = wo[c + 1];
            const float w10 = wo[H + c], w11 = wo[H + c + 1];
            const float v0 = fmaxf(acc[nt][0] + b0, 0.f);
            const float v1 = fmaxf(acc[nt][1] + b1, 0.f);
            const float v2 = fmaxf(acc[nt][2] + b0, 0.f);
            const float v3 = fmaxf(acc[nt][3] + b1, 0.f);
            o0a = fmaf(v0, w00, fmaf(v1, w01, o0a));
            o1a = fmaf(v0, w10, fmaf(v1, w11, o1a));
            o0b = fmaf(v2, w00, fmaf(v3, w01, o0b));
            o1b = fmaf(v2, w10, fmaf(v3, w11, o1b));
        }
#pragma unroll
        for (int m = 1; m <= 2; m <<= 1) {
            o0a += __shfl_xor_sync(0xFFFFFFFFu, o0a, m);
            o1a += __shfl_xor_sync(0xFFFFFFFFu, o1a, m);
            o0b += __shfl_xor_sync(0xFFFFFFFFu, o0b, m);
            o1b += __shfl_xor_sync(0xFFFFFFFFu, o1b, m);
        }
        if ((lane & 3) == 0) {
            const size_t row = (size_t)blockIdx.x * ROWS + 16 * wid + (lane >> 2);
            ((float2*)out)[row]     = make_float2(o0a + bo[0], o1a + bo[1]);
            ((float2*)out)[row + 8] = make_float2(o0b + bo[0], o1b + bo[1]);
        }
    }
}

// ============================================================================
// Launch
// ============================================================================
extern "C" void kernel_launch(void* const* d_in, const int* in_sizes, int n_in,
                              void* d_out, int out_size) {
    const float* x    = (const float*)d_in[0];
    const float* W    = (const float*)d_in[1];
    const float* b    = (const float*)d_in[2];
    const float* Wout = (const float*)d_in[3];
    const float* bout = (const float*)d_in[4];
    float* out = (float*)d_out;

    prep_w_kernel<<<L, 256>>>(W);

    cudaFuncSetAttribute(mlp_main, cudaFuncAttributeMaxDynamicSharedMemorySize, SMEM_BYTES);
    mlp_main<<<NROWS / ROWS, THREADS, SMEM_BYTES>>>(x, b, Wout, bout, out);
}